// round 11
// baseline (speedup 1.0000x reference)
#include <cuda_runtime.h>
#include <cuda_bf16.h>
#include <cstdint>

#define NNODES 20000
#define NEDGES 160000
#define F_IN   512
#define F_HID  512
#define F_OUT  256

// ---------------- scratch ----------------------------------------------------
__device__ int   g_is64;
__device__ int   g_indeg[NNODES];          // in-degree (for dinv, reference semantics)
__device__ int   g_outdeg[NNODES];         // out-degree (for src-CSR traversal)
__device__ int   g_rowptr[NNODES + 1];     // CSR by SRC
__device__ int   g_cursor[NNODES];
__device__ int   g_csr_dst[NEDGES];        // dst indices grouped by src
__device__ __align__(16) float g_dinv[NNODES];
__device__ __align__(16) float g_h1[(size_t)NNODES * F_HID];   // x@W1, then *dinv (= h')
__device__ __align__(16) float g_a1[(size_t)NNODES * F_HID];   // atomic accumulator / activated
__device__ __align__(16) float g_h2[(size_t)NNODES * F_OUT];   // (a1@W2)*dinv (= h')

// ---------------- preprocessing ---------------------------------------------
__global__ void detect_zero_kernel(const int* ei) {
    const int i = blockIdx.x * blockDim.x + threadIdx.x;
    if (i == 0) {
        int is64 = 1;
        for (int k = 1; k < 64; k += 2)
            if (ei[k] != 0) { is64 = 0; break; }
        g_is64 = is64;
    }
    if (i < NNODES) { g_indeg[i] = 0; g_outdeg[i] = 0; }
}

__global__ void deg_count_kernel(const void* ei) {
    const int e = blockIdx.x * blockDim.x + threadIdx.x;
    if (e < NEDGES) {
        int src, dst;
        if (g_is64) {
            const long long* p = (const long long*)ei;
            src = (int)p[e]; dst = (int)p[NEDGES + e];
        } else {
            const int* p = (const int*)ei;
            src = p[e]; dst = p[NEDGES + e];
        }
        atomicAdd(&g_indeg[dst], 1);
        atomicAdd(&g_outdeg[src], 1);
    }
}

// single block: scan OUT-degree -> rowptr/cursor; dinv from IN-degree
__global__ void scan_dinv_kernel() {
    __shared__ int part[1024];
    const int t = threadIdx.x;
    const int CH = (NNODES + 1023) / 1024;
    const int base = t * CH;
    int s = 0;
    for (int i = 0; i < CH; i++) {
        int idx = base + i;
        if (idx < NNODES) s += g_outdeg[idx];
    }
    part[t] = s;
    __syncthreads();
    for (int off = 1; off < 1024; off <<= 1) {
        int v = (t >= off) ? part[t - off] : 0;
        __syncthreads();
        part[t] += v;
        __syncthreads();
    }
    int run = (t > 0) ? part[t - 1] : 0;
    for (int i = 0; i < CH; i++) {
        int idx = base + i;
        if (idx < NNODES) {
            g_rowptr[idx] = run;
            g_cursor[idx] = run;
            g_dinv[idx] = rsqrtf(1.0f + (float)g_indeg[idx]);
            run += g_outdeg[idx];
        }
    }
    if (t == 1023) g_rowptr[NNODES] = part[1023];
}

__global__ void fill_kernel(const void* ei) {
    const int e = blockIdx.x * blockDim.x + threadIdx.x;
    if (e < NEDGES) {
        int src, dst;
        if (g_is64) {
            const long long* p = (const long long*)ei;
            src = (int)p[e]; dst = (int)p[NEDGES + e];
        } else {
            const int* p = (const int*)ei;
            src = p[e]; dst = p[NEDGES + e];
        }
        int pos = atomicAdd(&g_cursor[src], 1);
        g_csr_dst[pos] = dst;
    }
}

template <int F>
__global__ void scale_rows_kernel(float* __restrict__ h) {
    const int total4 = NNODES * F / 4;
    for (int idx = blockIdx.x * blockDim.x + threadIdx.x; idx < total4;
         idx += gridDim.x * blockDim.x) {
        const int node = idx / (F / 4);
        const float d = g_dinv[node];
        float4 v = reinterpret_cast<float4*>(h)[idx];
        v.x *= d; v.y *= d; v.z *= d; v.w *= d;
        reinterpret_cast<float4*>(h)[idx] = v;
    }
}

__global__ void zero_kernel(float* __restrict__ p, int n4) {
    for (int i = blockIdx.x * blockDim.x + threadIdx.x; i < n4;
         i += gridDim.x * blockDim.x)
        reinterpret_cast<float4*>(p)[i] = make_float4(0.f, 0.f, 0.f, 0.f);
}

// ---------------- SIMT fp32 GEMM, 128x128x8, 8x8/thread ---------------------
template <bool SCALE_OUT>
__global__ __launch_bounds__(256, 2)
void sgemm128_kernel(const float* __restrict__ A, const float* __restrict__ B,
                     float* __restrict__ C, int M, int N, int K) {
    constexpr int BM = 128, BN = 128, BK = 8;
    __shared__ float As[2][BK][BM];
    __shared__ float Bs[2][BK][BN];

    const int tid = threadIdx.x;
    const int block_row = blockIdx.y * BM;
    const int block_col = blockIdx.x * BN;

    const int a_row  = tid >> 1;
    const int a_col4 = (tid & 1) * 4;
    const int b_row  = tid >> 5;
    const int b_col4 = (tid & 31) * 4;

    const int ty = tid >> 4;
    const int tx = tid & 15;

    const int a_g_row = block_row + a_row;
    const bool a_ok = a_g_row < M;
    const float* a_ptr = A + (size_t)(a_ok ? a_g_row : 0) * K + a_col4;
    const float* b_ptr = B + (size_t)b_row * N + block_col + b_col4;

    float acc[8][8];
    #pragma unroll
    for (int i = 0; i < 8; i++)
        #pragma unroll
        for (int j = 0; j < 8; j++) acc[i][j] = 0.f;

    {
        float4 av = a_ok ? *reinterpret_cast<const float4*>(a_ptr)
                         : make_float4(0.f, 0.f, 0.f, 0.f);
        float4 bv = *reinterpret_cast<const float4*>(b_ptr);
        As[0][a_col4 + 0][a_row] = av.x;
        As[0][a_col4 + 1][a_row] = av.y;
        As[0][a_col4 + 2][a_row] = av.z;
        As[0][a_col4 + 3][a_row] = av.w;
        *reinterpret_cast<float4*>(&Bs[0][b_row][b_col4]) = bv;
    }
    __syncthreads();

    const int nsteps = K / BK;
    for (int k0 = 0; k0 < nsteps; k0++) {
        const int buf = k0 & 1;
        float4 av, bv;
        const bool has_next = (k0 + 1) < nsteps;
        if (has_next) {
            const float* ap = a_ptr + (size_t)(k0 + 1) * BK;
            av = a_ok ? *reinterpret_cast<const float4*>(ap)
                      : make_float4(0.f, 0.f, 0.f, 0.f);
            bv = *reinterpret_cast<const float4*>(b_ptr + (size_t)(k0 + 1) * BK * N);
        }

        #pragma unroll
        for (int k = 0; k < BK; k++) {
            float4 ra0 = *reinterpret_cast<const float4*>(&As[buf][k][ty * 4]);
            float4 ra1 = *reinterpret_cast<const float4*>(&As[buf][k][ty * 4 + 64]);
            float4 rb0 = *reinterpret_cast<const float4*>(&Bs[buf][k][tx * 4]);
            float4 rb1 = *reinterpret_cast<const float4*>(&Bs[buf][k][tx * 4 + 64]);
            const float ra[8] = {ra0.x, ra0.y, ra0.z, ra0.w, ra1.x, ra1.y, ra1.z, ra1.w};
            const float rb[8] = {rb0.x, rb0.y, rb0.z, rb0.w, rb1.x, rb1.y, rb1.z, rb1.w};
            #pragma unroll
            for (int i = 0; i < 8; i++)
                #pragma unroll
                for (int j = 0; j < 8; j++) acc[i][j] += ra[i] * rb[j];
        }

        if (has_next) {
            const int nb = buf ^ 1;
            As[nb][a_col4 + 0][a_row] = av.x;
            As[nb][a_col4 + 1][a_row] = av.y;
            As[nb][a_col4 + 2][a_row] = av.z;
            As[nb][a_col4 + 3][a_row] = av.w;
            *reinterpret_cast<float4*>(&Bs[nb][b_row][b_col4]) = bv;
            __syncthreads();
        }
    }

    #pragma unroll
    for (int i = 0; i < 8; i++) {
        const int lr = (i < 4) ? (ty * 4 + i) : (64 + ty * 4 + i - 4);
        const int gr = block_row + lr;
        if (gr < M) {
            const float d = SCALE_OUT ? g_dinv[gr] : 1.0f;
            float4 v0 = make_float4(acc[i][0] * d, acc[i][1] * d, acc[i][2] * d, acc[i][3] * d);
            float4 v1 = make_float4(acc[i][4] * d, acc[i][5] * d, acc[i][6] * d, acc[i][7] * d);
            *reinterpret_cast<float4*>(C + (size_t)gr * N + block_col + tx * 4) = v0;
            *reinterpret_cast<float4*>(C + (size_t)gr * N + block_col + 64 + tx * 4) = v1;
        }
    }
}

// ---------------- PUSH scatter: warp per src node ----------------------------
// Row h'[s] loaded ONCE (streaming, L1-resident across the dst loop), then
// atomically added into each out-neighbor's accumulator (REDG, no return).
template <int F>
__global__ void scatter_kernel(const float* __restrict__ h, float* __restrict__ acc) {
    constexpr int NV = F / 128;              // float4 per lane (4 or 2)
    const int w    = threadIdx.x >> 5;       // 8 warps/block
    const int lane = threadIdx.x & 31;
    const int s = blockIdx.x * 8 + w;
    if (s >= NNODES) return;

    float4 row[NV];
    const float4* hp = reinterpret_cast<const float4*>(h + (size_t)s * F);
    #pragma unroll
    for (int i = 0; i < NV; i++) row[i] = hp[lane + 32 * i];

    const int beg = g_rowptr[s];
    const int end = g_rowptr[s + 1];
    for (int j = beg; j < end; j++) {
        const int dst = __ldg(&g_csr_dst[j]);
        float* ap = acc + (size_t)dst * F;
        #pragma unroll
        for (int i = 0; i < NV; i++) {
            const int c = (lane + 32 * i) * 4;
            atomicAdd(ap + c + 0, row[i].x);
            atomicAdd(ap + c + 1, row[i].y);
            atomicAdd(ap + c + 2, row[i].z);
            atomicAdd(ap + c + 3, row[i].w);
        }
    }
}

// ---------------- finalize: out = relu(dinv[v]*(acc + h'[v]) + b) ------------
template <int F>
__global__ void finalize_kernel(const float* __restrict__ h,
                                const float* __restrict__ bias,
                                float* __restrict__ io) {
    const int total4 = NNODES * F / 4;
    for (int idx = blockIdx.x * blockDim.x + threadIdx.x; idx < total4;
         idx += gridDim.x * blockDim.x) {
        const int node = idx / (F / 4);
        const int c4 = idx % (F / 4);
        const float dv = g_dinv[node];
        float4 a = reinterpret_cast<const float4*>(io)[idx];
        float4 hv = reinterpret_cast<const float4*>(h)[idx];
        float4 b = reinterpret_cast<const float4*>(bias)[c4];
        float4 o;
        o.x = fmaxf((a.x + hv.x) * dv + b.x, 0.f);
        o.y = fmaxf((a.y + hv.y) * dv + b.y, 0.f);
        o.z = fmaxf((a.z + hv.z) * dv + b.z, 0.f);
        o.w = fmaxf((a.w + hv.w) * dv + b.w, 0.f);
        reinterpret_cast<float4*>(io)[idx] = o;
    }
}

// ---------------- launch ----------------------------------------------------
extern "C" void kernel_launch(void* const* d_in, const int* in_sizes, int n_in,
                              void* d_out, int out_size) {
    const float* x  = (const float*)d_in[0];
    const void*  ei = d_in[1];
    const float* W1 = (const float*)d_in[2];
    const float* b1 = (const float*)d_in[3];
    const float* W2 = (const float*)d_in[4];
    const float* b2 = (const float*)d_in[5];
    float* out = (float*)d_out;

    detect_zero_kernel<<<(NNODES + 255) / 256, 256>>>((const int*)ei);   // 0
    deg_count_kernel<<<(NEDGES + 255) / 256, 256>>>(ei);                 // 1
    scan_dinv_kernel<<<1, 1024>>>();                                     // 2
    fill_kernel<<<(NEDGES + 255) / 256, 256>>>(ei);                      // 3

    // --- layer 1 ---
    {
        dim3 grid(F_HID / 128, (NNODES + 127) / 128);
        sgemm128_kernel<false><<<grid, 256>>>(x, W1, g_h1, NNODES, F_HID, F_IN);
    }
    scale_rows_kernel<F_HID><<<2048, 256>>>(g_h1);                // h1 = h' (prescaled)
    zero_kernel<<<2048, 256>>>(g_a1, NNODES * F_HID / 4);
    scatter_kernel<F_HID><<<(NNODES + 7) / 8, 256>>>(g_h1, g_a1);
    finalize_kernel<F_HID><<<2048, 256>>>(g_h1, b1, g_a1);        // a1 = relu(...)

    // --- layer 2 ---
    {
        dim3 grid(F_OUT / 128, (NNODES + 127) / 128);
        sgemm128_kernel<true><<<grid, 256>>>(g_a1, W2, g_h2, NNODES, F_OUT, F_HID);
    }
    zero_kernel<<<2048, 256>>>(out, NNODES * F_OUT / 4);
    scatter_kernel<F_OUT><<<(NNODES + 7) / 8, 256>>>(g_h2, out);
    finalize_kernel<F_OUT><<<2048, 256>>>(g_h2, b2, out);
}

// round 12
// speedup vs baseline: 5.7832x; 5.7832x over previous
#include <cuda_runtime.h>
#include <cuda_fp16.h>
#include <cstdint>

#define NNODES 20000
#define NEDGES 160000
#define F_IN   512
#define F_HID  512
#define F_OUT  256

// ---------------- scratch ----------------------------------------------------
__device__ int   g_is64;
__device__ int   g_deg[NNODES];            // in-degree
__device__ int   g_rowptr[NNODES + 1];     // CSR by dst
__device__ int   g_cursor[NNODES];
__device__ int   g_srcs[NEDGES];
__device__ __align__(16) float  g_dinv[NNODES];
__device__ __align__(16) __half g_h1h[(size_t)NNODES * F_HID];  // (x@W1)*dinv, fp16
__device__ __align__(16) float  g_a1[(size_t)NNODES * F_HID];   // layer-1 activation
__device__ __align__(16) float  g_h2[(size_t)NNODES * F_OUT];   // (a1@W2)*dinv, fp32

// ---------------- preprocessing ---------------------------------------------
__global__ void detect_zero_kernel(const int* ei) {
    const int i = blockIdx.x * blockDim.x + threadIdx.x;
    if (i == 0) {
        int is64 = 1;
        for (int k = 1; k < 64; k += 2)
            if (ei[k] != 0) { is64 = 0; break; }
        g_is64 = is64;
    }
    if (i < NNODES) g_deg[i] = 0;
}

__global__ void deg_count_kernel(const void* ei) {
    const int e = blockIdx.x * blockDim.x + threadIdx.x;
    if (e < NEDGES) {
        int dst;
        if (g_is64) dst = (int)((const long long*)ei)[NEDGES + e];
        else        dst = ((const int*)ei)[NEDGES + e];
        atomicAdd(&g_deg[dst], 1);
    }
}

__global__ void scan_dinv_kernel() {
    __shared__ int part[1024];
    const int t = threadIdx.x;
    const int CH = (NNODES + 1023) / 1024;
    const int base = t * CH;
    int s = 0;
    for (int i = 0; i < CH; i++) {
        int idx = base + i;
        if (idx < NNODES) s += g_deg[idx];
    }
    part[t] = s;
    __syncthreads();
    for (int off = 1; off < 1024; off <<= 1) {
        int v = (t >= off) ? part[t - off] : 0;
        __syncthreads();
        part[t] += v;
        __syncthreads();
    }
    int run = (t > 0) ? part[t - 1] : 0;
    for (int i = 0; i < CH; i++) {
        int idx = base + i;
        if (idx < NNODES) {
            g_rowptr[idx] = run;
            g_cursor[idx] = run;
            g_dinv[idx] = rsqrtf(1.0f + (float)g_deg[idx]);
            run += g_deg[idx];
        }
    }
    if (t == 1023) g_rowptr[NNODES] = part[1023];
}

__global__ void fill_kernel(const void* ei) {
    const int e = blockIdx.x * blockDim.x + threadIdx.x;
    if (e < NEDGES) {
        int src, dst;
        if (g_is64) {
            const long long* p = (const long long*)ei;
            src = (int)p[e]; dst = (int)p[NEDGES + e];
        } else {
            const int* p = (const int*)ei;
            src = p[e]; dst = p[NEDGES + e];
        }
        int pos = atomicAdd(&g_cursor[dst], 1);
        g_srcs[pos] = src;
    }
}

// ---------------- SIMT fp32 GEMM, 128x128x8, 8x8/thread ---------------------
// OUT_MODE: 1 = fp32 out scaled by dinv[row]; 2 = fp16 out scaled by dinv[row].
template <int OUT_MODE>
__global__ __launch_bounds__(256, 2)
void sgemm128_kernel(const float* __restrict__ A, const float* __restrict__ B,
                     void* __restrict__ Cv, int M, int N, int K) {
    constexpr int BM = 128, BN = 128, BK = 8;
    __shared__ float As[2][BK][BM];
    __shared__ float Bs[2][BK][BN];

    const int tid = threadIdx.x;
    const int block_row = blockIdx.y * BM;
    const int block_col = blockIdx.x * BN;

    const int a_row  = tid >> 1;
    const int a_col4 = (tid & 1) * 4;
    const int b_row  = tid >> 5;
    const int b_col4 = (tid & 31) * 4;

    const int ty = tid >> 4;
    const int tx = tid & 15;

    const int a_g_row = block_row + a_row;
    const bool a_ok = a_g_row < M;
    const float* a_ptr = A + (size_t)(a_ok ? a_g_row : 0) * K + a_col4;
    const float* b_ptr = B + (size_t)b_row * N + block_col + b_col4;

    float acc[8][8];
    #pragma unroll
    for (int i = 0; i < 8; i++)
        #pragma unroll
        for (int j = 0; j < 8; j++) acc[i][j] = 0.f;

    {
        float4 av = a_ok ? *reinterpret_cast<const float4*>(a_ptr)
                         : make_float4(0.f, 0.f, 0.f, 0.f);
        float4 bv = *reinterpret_cast<const float4*>(b_ptr);
        As[0][a_col4 + 0][a_row] = av.x;
        As[0][a_col4 + 1][a_row] = av.y;
        As[0][a_col4 + 2][a_row] = av.z;
        As[0][a_col4 + 3][a_row] = av.w;
        *reinterpret_cast<float4*>(&Bs[0][b_row][b_col4]) = bv;
    }
    __syncthreads();

    const int nsteps = K / BK;
    for (int k0 = 0; k0 < nsteps; k0++) {
        const int buf = k0 & 1;
        float4 av, bv;
        const bool has_next = (k0 + 1) < nsteps;
        if (has_next) {
            const float* ap = a_ptr + (size_t)(k0 + 1) * BK;
            av = a_ok ? *reinterpret_cast<const float4*>(ap)
                      : make_float4(0.f, 0.f, 0.f, 0.f);
            bv = *reinterpret_cast<const float4*>(b_ptr + (size_t)(k0 + 1) * BK * N);
        }

        #pragma unroll
        for (int k = 0; k < BK; k++) {
            float4 ra0 = *reinterpret_cast<const float4*>(&As[buf][k][ty * 4]);
            float4 ra1 = *reinterpret_cast<const float4*>(&As[buf][k][ty * 4 + 64]);
            float4 rb0 = *reinterpret_cast<const float4*>(&Bs[buf][k][tx * 4]);
            float4 rb1 = *reinterpret_cast<const float4*>(&Bs[buf][k][tx * 4 + 64]);
            const float ra[8] = {ra0.x, ra0.y, ra0.z, ra0.w, ra1.x, ra1.y, ra1.z, ra1.w};
            const float rb[8] = {rb0.x, rb0.y, rb0.z, rb0.w, rb1.x, rb1.y, rb1.z, rb1.w};
            #pragma unroll
            for (int i = 0; i < 8; i++)
                #pragma unroll
                for (int j = 0; j < 8; j++) acc[i][j] += ra[i] * rb[j];
        }

        if (has_next) {
            const int nb = buf ^ 1;
            As[nb][a_col4 + 0][a_row] = av.x;
            As[nb][a_col4 + 1][a_row] = av.y;
            As[nb][a_col4 + 2][a_row] = av.z;
            As[nb][a_col4 + 3][a_row] = av.w;
            *reinterpret_cast<float4*>(&Bs[nb][b_row][b_col4]) = bv;
            __syncthreads();
        }
    }

    #pragma unroll
    for (int i = 0; i < 8; i++) {
        const int lr = (i < 4) ? (ty * 4 + i) : (64 + ty * 4 + i - 4);
        const int gr = block_row + lr;
        if (gr < M) {
            const float d = g_dinv[gr];
            if (OUT_MODE == 1) {
                float* C = (float*)Cv;
                float4 v0 = make_float4(acc[i][0] * d, acc[i][1] * d, acc[i][2] * d, acc[i][3] * d);
                float4 v1 = make_float4(acc[i][4] * d, acc[i][5] * d, acc[i][6] * d, acc[i][7] * d);
                *reinterpret_cast<float4*>(C + (size_t)gr * N + block_col + tx * 4) = v0;
                *reinterpret_cast<float4*>(C + (size_t)gr * N + block_col + 64 + tx * 4) = v1;
            } else {
                __half* C = (__half*)Cv;
                __half2 p0 = __floats2half2_rn(acc[i][0] * d, acc[i][1] * d);
                __half2 p1 = __floats2half2_rn(acc[i][2] * d, acc[i][3] * d);
                __half2 p2 = __floats2half2_rn(acc[i][4] * d, acc[i][5] * d);
                __half2 p3 = __floats2half2_rn(acc[i][6] * d, acc[i][7] * d);
                __half2* c0 = reinterpret_cast<__half2*>(C + (size_t)gr * N + block_col + tx * 4);
                c0[0] = p0; c0[1] = p1;
                __half2* c1 = reinterpret_cast<__half2*>(C + (size_t)gr * N + block_col + 64 + tx * 4);
                c1[0] = p2; c1[1] = p3;
            }
        }
    }
}

// ---------------- fp16 pull aggregation (layer 1) ----------------------------
// a1[v] = relu( dinv[v] * ( sum_{src} h'[src] + h'[v] ) + b ), h' fp16.
// Warp per node; lane reads uint2 = 4 halves per chunk; 4 chunks cover F=512.
__global__ __launch_bounds__(256)
void aggregate_h16_kernel(const __half* __restrict__ h,
                          const float* __restrict__ bias,
                          float* __restrict__ out) {
    constexpr int F = F_HID;
    constexpr int NC = F / 128;              // 4 chunks (128 halves each)
    const int w    = threadIdx.x >> 5;
    const int lane = threadIdx.x & 31;
    const int v = blockIdx.x * 8 + w;
    if (v >= NNODES) return;

    const float dv = g_dinv[v];

    float2 acc[NC][2];
    {
        const uint2* hv = reinterpret_cast<const uint2*>(h + (size_t)v * F);
        #pragma unroll
        for (int i = 0; i < NC; i++) {
            uint2 u = __ldg(&hv[lane + 32 * i]);
            acc[i][0] = __half22float2(*reinterpret_cast<__half2*>(&u.x));
            acc[i][1] = __half22float2(*reinterpret_cast<__half2*>(&u.y));
        }
    }

    const int beg = g_rowptr[v];
    const int end = g_rowptr[v + 1];
    int j = beg;
    for (; j + 2 <= end; j += 2) {
        const int s0 = __ldg(&g_srcs[j + 0]);
        const int s1 = __ldg(&g_srcs[j + 1]);
        const uint2* p0 = reinterpret_cast<const uint2*>(h + (size_t)s0 * F);
        const uint2* p1 = reinterpret_cast<const uint2*>(h + (size_t)s1 * F);
        #pragma unroll
        for (int i = 0; i < NC; i++) {
            const int c = lane + 32 * i;
            uint2 u0 = __ldg(&p0[c]);
            uint2 u1 = __ldg(&p1[c]);
            float2 a0 = __half22float2(*reinterpret_cast<__half2*>(&u0.x));
            float2 b0 = __half22float2(*reinterpret_cast<__half2*>(&u0.y));
            float2 a1 = __half22float2(*reinterpret_cast<__half2*>(&u1.x));
            float2 b1 = __half22float2(*reinterpret_cast<__half2*>(&u1.y));
            acc[i][0].x += a0.x + a1.x;
            acc[i][0].y += a0.y + a1.y;
            acc[i][1].x += b0.x + b1.x;
            acc[i][1].y += b0.y + b1.y;
        }
    }
    for (; j < end; j++) {
        const int s = __ldg(&g_srcs[j]);
        const uint2* p = reinterpret_cast<const uint2*>(h + (size_t)s * F);
        #pragma unroll
        for (int i = 0; i < NC; i++) {
            uint2 u = __ldg(&p[lane + 32 * i]);
            float2 a = __half22float2(*reinterpret_cast<__half2*>(&u.x));
            float2 b = __half22float2(*reinterpret_cast<__half2*>(&u.y));
            acc[i][0].x += a.x; acc[i][0].y += a.y;
            acc[i][1].x += b.x; acc[i][1].y += b.y;
        }
    }

    float* op = out + (size_t)v * F;
    #pragma unroll
    for (int i = 0; i < NC; i++) {
        const int c = (lane + 32 * i) * 4;
        float4 b = *reinterpret_cast<const float4*>(bias + c);
        float4 o;
        o.x = fmaxf(acc[i][0].x * dv + b.x, 0.f);
        o.y = fmaxf(acc[i][0].y * dv + b.y, 0.f);
        o.z = fmaxf(acc[i][1].x * dv + b.z, 0.f);
        o.w = fmaxf(acc[i][1].y * dv + b.w, 0.f);
        *reinterpret_cast<float4*>(op + c) = o;
    }
}

// ---------------- fp32 pull aggregation (layer 2, UNCHANGED R8) --------------
template <int F>
__global__ void aggregate_warp_kernel(const float* __restrict__ h,
                                      const float* __restrict__ bias,
                                      float* __restrict__ out) {
    constexpr int NV = F / 128;
    const int w    = threadIdx.x >> 5;
    const int lane = threadIdx.x & 31;
    const int v = blockIdx.x * 8 + w;
    if (v >= NNODES) return;

    const float dv = g_dinv[v];

    float4 acc[NV];
    {
        const float4* hv = reinterpret_cast<const float4*>(h + (size_t)v * F);
        #pragma unroll
        for (int i = 0; i < NV; i++) acc[i] = __ldg(&hv[lane + 32 * i]);
    }

    const int beg = g_rowptr[v];
    const int end = g_rowptr[v + 1];
    int j = beg;
    for (; j + 4 <= end; j += 4) {
        const int s0 = __ldg(&g_srcs[j + 0]);
        const int s1 = __ldg(&g_srcs[j + 1]);
        const int s2 = __ldg(&g_srcs[j + 2]);
        const int s3 = __ldg(&g_srcs[j + 3]);
        const float4* p0 = reinterpret_cast<const float4*>(h + (size_t)s0 * F);
        const float4* p1 = reinterpret_cast<const float4*>(h + (size_t)s1 * F);
        const float4* p2 = reinterpret_cast<const float4*>(h + (size_t)s2 * F);
        const float4* p3 = reinterpret_cast<const float4*>(h + (size_t)s3 * F);
        #pragma unroll
        for (int i = 0; i < NV; i++) {
            const int c = lane + 32 * i;
            float4 t0 = __ldg(&p0[c]);
            float4 t1 = __ldg(&p1[c]);
            float4 t2 = __ldg(&p2[c]);
            float4 t3 = __ldg(&p3[c]);
            acc[i].x += (t0.x + t1.x) + (t2.x + t3.x);
            acc[i].y += (t0.y + t1.y) + (t2.y + t3.y);
            acc[i].z += (t0.z + t1.z) + (t2.z + t3.z);
            acc[i].w += (t0.w + t1.w) + (t2.w + t3.w);
        }
    }
    for (; j < end; j++) {
        const int s = __ldg(&g_srcs[j]);
        const float4* p = reinterpret_cast<const float4*>(h + (size_t)s * F);
        #pragma unroll
        for (int i = 0; i < NV; i++) {
            float4 t = __ldg(&p[lane + 32 * i]);
            acc[i].x += t.x; acc[i].y += t.y; acc[i].z += t.z; acc[i].w += t.w;
        }
    }

    const float4* bptr = reinterpret_cast<const float4*>(bias);
    float4* optr = reinterpret_cast<float4*>(out + (size_t)v * F);
    #pragma unroll
    for (int i = 0; i < NV; i++) {
        float4 b = bptr[lane + 32 * i];
        float4 o;
        o.x = fmaxf(acc[i].x * dv + b.x, 0.f);
        o.y = fmaxf(acc[i].y * dv + b.y, 0.f);
        o.z = fmaxf(acc[i].z * dv + b.z, 0.f);
        o.w = fmaxf(acc[i].w * dv + b.w, 0.f);
        optr[lane + 32 * i] = o;
    }
}

// ---------------- launch ----------------------------------------------------
extern "C" void kernel_launch(void* const* d_in, const int* in_sizes, int n_in,
                              void* d_out, int out_size) {
    const float* x  = (const float*)d_in[0];
    const void*  ei = d_in[1];
    const float* W1 = (const float*)d_in[2];
    const float* b1 = (const float*)d_in[3];
    const float* W2 = (const float*)d_in[4];
    const float* b2 = (const float*)d_in[5];
    float* out = (float*)d_out;

    detect_zero_kernel<<<(NNODES + 255) / 256, 256>>>((const int*)ei);   // 0
    deg_count_kernel<<<(NEDGES + 255) / 256, 256>>>(ei);                 // 1
    scan_dinv_kernel<<<1, 1024>>>();                                     // 2

    {   // 3 (ncu capture): h1' = (x@W1)*dinv -> fp16
        dim3 grid(F_HID / 128, (NNODES + 127) / 128);
        sgemm128_kernel<2><<<grid, 256>>>(x, W1, (void*)g_h1h, NNODES, F_HID, F_IN);
    }
    fill_kernel<<<(NEDGES + 255) / 256, 256>>>(ei);                      // 4
    aggregate_h16_kernel<<<(NNODES + 7) / 8, 256>>>(g_h1h, b1, g_a1);    // 5

    {   // 6: h2' = (a1@W2)*dinv -> fp32
        dim3 grid(F_OUT / 128, (NNODES + 127) / 128);
        sgemm128_kernel<1><<<grid, 256>>>(g_a1, W2, (void*)g_h2, NNODES, F_OUT, F_HID);
    }
    aggregate_warp_kernel<F_OUT><<<(NNODES + 7) / 8, 256>>>(g_h2, b2, out);  // 7
}

// round 13
// speedup vs baseline: 6.4894x; 1.1221x over previous
#include <cuda_runtime.h>
#include <cuda_fp16.h>
#include <cstdint>

#define NNODES 20000
#define NEDGES 160000
#define F_IN   512
#define F_HID  512
#define F_OUT  256

// ---------------- scratch ----------------------------------------------------
__device__ int   g_is64;
__device__ int   g_deg[NNODES];            // in-degree
__device__ int   g_rowptr[NNODES + 1];     // CSR by dst
__device__ int   g_cursor[NNODES];
__device__ int   g_srcs[NEDGES];
__device__ __align__(16) float  g_dinv[NNODES];
__device__ __align__(16) __half g_h1h[(size_t)NNODES * F_HID];  // (x@W1)*dinv, fp16
__device__ __align__(16) float  g_a1[(size_t)NNODES * F_HID];   // layer-1 activation
__device__ __align__(16) __half g_h2h[(size_t)NNODES * F_OUT];  // (a1@W2)*dinv, fp16

// ---------------- preprocessing ---------------------------------------------
__global__ void detect_zero_kernel(const int* ei) {
    const int i = blockIdx.x * blockDim.x + threadIdx.x;
    if (i == 0) {
        int is64 = 1;
        for (int k = 1; k < 64; k += 2)
            if (ei[k] != 0) { is64 = 0; break; }
        g_is64 = is64;
    }
    if (i < NNODES) g_deg[i] = 0;
}

__global__ void deg_count_kernel(const void* ei) {
    const int e = blockIdx.x * blockDim.x + threadIdx.x;
    if (e < NEDGES) {
        int dst;
        if (g_is64) dst = (int)((const long long*)ei)[NEDGES + e];
        else        dst = ((const int*)ei)[NEDGES + e];
        atomicAdd(&g_deg[dst], 1);
    }
}

__global__ void scan_dinv_kernel() {
    __shared__ int part[1024];
    const int t = threadIdx.x;
    const int CH = (NNODES + 1023) / 1024;
    const int base = t * CH;
    int s = 0;
    for (int i = 0; i < CH; i++) {
        int idx = base + i;
        if (idx < NNODES) s += g_deg[idx];
    }
    part[t] = s;
    __syncthreads();
    for (int off = 1; off < 1024; off <<= 1) {
        int v = (t >= off) ? part[t - off] : 0;
        __syncthreads();
        part[t] += v;
        __syncthreads();
    }
    int run = (t > 0) ? part[t - 1] : 0;
    for (int i = 0; i < CH; i++) {
        int idx = base + i;
        if (idx < NNODES) {
            g_rowptr[idx] = run;
            g_cursor[idx] = run;
            g_dinv[idx] = rsqrtf(1.0f + (float)g_deg[idx]);
            run += g_deg[idx];
        }
    }
    if (t == 1023) g_rowptr[NNODES] = part[1023];
}

__global__ void fill_kernel(const void* ei) {
    const int e = blockIdx.x * blockDim.x + threadIdx.x;
    if (e < NEDGES) {
        int src, dst;
        if (g_is64) {
            const long long* p = (const long long*)ei;
            src = (int)p[e]; dst = (int)p[NEDGES + e];
        } else {
            const int* p = (const int*)ei;
            src = p[e]; dst = p[NEDGES + e];
        }
        int pos = atomicAdd(&g_cursor[dst], 1);
        g_srcs[pos] = src;
    }
}

// ---------------- SIMT fp32 GEMM, 128x128x8, 8x8/thread ---------------------
// Output: fp16, scaled by dinv[row].
__global__ __launch_bounds__(256, 2)
void sgemm128_h16_kernel(const float* __restrict__ A, const float* __restrict__ B,
                         __half* __restrict__ C, int M, int N, int K) {
    constexpr int BM = 128, BN = 128, BK = 8;
    __shared__ float As[2][BK][BM];
    __shared__ float Bs[2][BK][BN];

    const int tid = threadIdx.x;
    const int block_row = blockIdx.y * BM;
    const int block_col = blockIdx.x * BN;

    const int a_row  = tid >> 1;
    const int a_col4 = (tid & 1) * 4;
    const int b_row  = tid >> 5;
    const int b_col4 = (tid & 31) * 4;

    const int ty = tid >> 4;
    const int tx = tid & 15;

    const int a_g_row = block_row + a_row;
    const bool a_ok = a_g_row < M;
    const float* a_ptr = A + (size_t)(a_ok ? a_g_row : 0) * K + a_col4;
    const float* b_ptr = B + (size_t)b_row * N + block_col + b_col4;

    float acc[8][8];
    #pragma unroll
    for (int i = 0; i < 8; i++)
        #pragma unroll
        for (int j = 0; j < 8; j++) acc[i][j] = 0.f;

    {
        float4 av = a_ok ? *reinterpret_cast<const float4*>(a_ptr)
                         : make_float4(0.f, 0.f, 0.f, 0.f);
        float4 bv = *reinterpret_cast<const float4*>(b_ptr);
        As[0][a_col4 + 0][a_row] = av.x;
        As[0][a_col4 + 1][a_row] = av.y;
        As[0][a_col4 + 2][a_row] = av.z;
        As[0][a_col4 + 3][a_row] = av.w;
        *reinterpret_cast<float4*>(&Bs[0][b_row][b_col4]) = bv;
    }
    __syncthreads();

    const int nsteps = K / BK;
    for (int k0 = 0; k0 < nsteps; k0++) {
        const int buf = k0 & 1;
        float4 av, bv;
        const bool has_next = (k0 + 1) < nsteps;
        if (has_next) {
            const float* ap = a_ptr + (size_t)(k0 + 1) * BK;
            av = a_ok ? *reinterpret_cast<const float4*>(ap)
                      : make_float4(0.f, 0.f, 0.f, 0.f);
            bv = *reinterpret_cast<const float4*>(b_ptr + (size_t)(k0 + 1) * BK * N);
        }

        #pragma unroll
        for (int k = 0; k < BK; k++) {
            float4 ra0 = *reinterpret_cast<const float4*>(&As[buf][k][ty * 4]);
            float4 ra1 = *reinterpret_cast<const float4*>(&As[buf][k][ty * 4 + 64]);
            float4 rb0 = *reinterpret_cast<const float4*>(&Bs[buf][k][tx * 4]);
            float4 rb1 = *reinterpret_cast<const float4*>(&Bs[buf][k][tx * 4 + 64]);
            const float ra[8] = {ra0.x, ra0.y, ra0.z, ra0.w, ra1.x, ra1.y, ra1.z, ra1.w};
            const float rb[8] = {rb0.x, rb0.y, rb0.z, rb0.w, rb1.x, rb1.y, rb1.z, rb1.w};
            #pragma unroll
            for (int i = 0; i < 8; i++)
                #pragma unroll
                for (int j = 0; j < 8; j++) acc[i][j] += ra[i] * rb[j];
        }

        if (has_next) {
            const int nb = buf ^ 1;
            As[nb][a_col4 + 0][a_row] = av.x;
            As[nb][a_col4 + 1][a_row] = av.y;
            As[nb][a_col4 + 2][a_row] = av.z;
            As[nb][a_col4 + 3][a_row] = av.w;
            *reinterpret_cast<float4*>(&Bs[nb][b_row][b_col4]) = bv;
            __syncthreads();
        }
    }

    #pragma unroll
    for (int i = 0; i < 8; i++) {
        const int lr = (i < 4) ? (ty * 4 + i) : (64 + ty * 4 + i - 4);
        const int gr = block_row + lr;
        if (gr < M) {
            const float d = g_dinv[gr];
            __half2 p0 = __floats2half2_rn(acc[i][0] * d, acc[i][1] * d);
            __half2 p1 = __floats2half2_rn(acc[i][2] * d, acc[i][3] * d);
            __half2 p2 = __floats2half2_rn(acc[i][4] * d, acc[i][5] * d);
            __half2 p3 = __floats2half2_rn(acc[i][6] * d, acc[i][7] * d);
            __half2* c0 = reinterpret_cast<__half2*>(C + (size_t)gr * N + block_col + tx * 4);
            c0[0] = p0; c0[1] = p1;
            __half2* c1 = reinterpret_cast<__half2*>(C + (size_t)gr * N + block_col + 64 + tx * 4);
            c1[0] = p2; c1[1] = p3;
        }
    }
}

// ---------------- fp16 pull aggregation --------------------------------------
// out[v] = relu( dinv[v] * ( sum_{src} h'[src] + h'[v] ) + b ), h' fp16 rows.
// Warp per node; lane reads uint2 = 4 halves per chunk; NC = F/128 chunks.
template <int F>
__global__ __launch_bounds__(256)
void aggregate_h16_kernel(const __half* __restrict__ h,
                          const float* __restrict__ bias,
                          float* __restrict__ out) {
    constexpr int NC = F / 128;
    const int w    = threadIdx.x >> 5;
    const int lane = threadIdx.x & 31;
    const int v = blockIdx.x * 8 + w;
    if (v >= NNODES) return;

    const float dv = g_dinv[v];

    float2 acc[NC][2];
    {
        const uint2* hv = reinterpret_cast<const uint2*>(h + (size_t)v * F);
        #pragma unroll
        for (int i = 0; i < NC; i++) {
            uint2 u = __ldg(&hv[lane + 32 * i]);
            acc[i][0] = __half22float2(*reinterpret_cast<__half2*>(&u.x));
            acc[i][1] = __half22float2(*reinterpret_cast<__half2*>(&u.y));
        }
    }

    const int beg = g_rowptr[v];
    const int end = g_rowptr[v + 1];
    int j = beg;
    for (; j + 2 <= end; j += 2) {
        const int s0 = __ldg(&g_srcs[j + 0]);
        const int s1 = __ldg(&g_srcs[j + 1]);
        const uint2* p0 = reinterpret_cast<const uint2*>(h + (size_t)s0 * F);
        const uint2* p1 = reinterpret_cast<const uint2*>(h + (size_t)s1 * F);
        #pragma unroll
        for (int i = 0; i < NC; i++) {
            const int c = lane + 32 * i;
            uint2 u0 = __ldg(&p0[c]);
            uint2 u1 = __ldg(&p1[c]);
            float2 a0 = __half22float2(*reinterpret_cast<__half2*>(&u0.x));
            float2 b0 = __half22float2(*reinterpret_cast<__half2*>(&u0.y));
            float2 a1 = __half22float2(*reinterpret_cast<__half2*>(&u1.x));
            float2 b1 = __half22float2(*reinterpret_cast<__half2*>(&u1.y));
            acc[i][0].x += a0.x + a1.x;
            acc[i][0].y += a0.y + a1.y;
            acc[i][1].x += b0.x + b1.x;
            acc[i][1].y += b0.y + b1.y;
        }
    }
    for (; j < end; j++) {
        const int s = __ldg(&g_srcs[j]);
        const uint2* p = reinterpret_cast<const uint2*>(h + (size_t)s * F);
        #pragma unroll
        for (int i = 0; i < NC; i++) {
            uint2 u = __ldg(&p[lane + 32 * i]);
            float2 a = __half22float2(*reinterpret_cast<__half2*>(&u.x));
            float2 b = __half22float2(*reinterpret_cast<__half2*>(&u.y));
            acc[i][0].x += a.x; acc[i][0].y += a.y;
            acc[i][1].x += b.x; acc[i][1].y += b.y;
        }
    }

    float* op = out + (size_t)v * F;
    #pragma unroll
    for (int i = 0; i < NC; i++) {
        const int c = (lane + 32 * i) * 4;
        float4 b = *reinterpret_cast<const float4*>(bias + c);
        float4 o;
        o.x = fmaxf(acc[i][0].x * dv + b.x, 0.f);
        o.y = fmaxf(acc[i][0].y * dv + b.y, 0.f);
        o.z = fmaxf(acc[i][1].x * dv + b.z, 0.f);
        o.w = fmaxf(acc[i][1].y * dv + b.w, 0.f);
        *reinterpret_cast<float4*>(op + c) = o;
    }
}

// ---------------- launch ----------------------------------------------------
extern "C" void kernel_launch(void* const* d_in, const int* in_sizes, int n_in,
                              void* d_out, int out_size) {
    const float* x  = (const float*)d_in[0];
    const void*  ei = d_in[1];
    const float* W1 = (const float*)d_in[2];
    const float* b1 = (const float*)d_in[3];
    const float* W2 = (const float*)d_in[4];
    const float* b2 = (const float*)d_in[5];
    float* out = (float*)d_out;

    detect_zero_kernel<<<(NNODES + 255) / 256, 256>>>((const int*)ei);   // 0
    deg_count_kernel<<<(NEDGES + 255) / 256, 256>>>(ei);                 // 1
    scan_dinv_kernel<<<1, 1024>>>();                                     // 2

    {   // 3 (ncu capture): h1' = (x@W1)*dinv -> fp16
        dim3 grid(F_HID / 128, (NNODES + 127) / 128);
        sgemm128_h16_kernel<<<grid, 256>>>(x, W1, g_h1h, NNODES, F_HID, F_IN);
    }
    fill_kernel<<<(NEDGES + 255) / 256, 256>>>(ei);                      // 4
    aggregate_h16_kernel<F_HID><<<(NNODES + 7) / 8, 256>>>(g_h1h, b1, g_a1);   // 5

    {   // 6: h2' = (a1@W2)*dinv -> fp16
        dim3 grid(F_OUT / 128, (NNODES + 127) / 128);
        sgemm128_h16_kernel<<<grid, 256>>>(g_a1, W2, g_h2h, NNODES, F_OUT, F_HID);
    }
    aggregate_h16_kernel<F_OUT><<<(NNODES + 7) / 8, 256>>>(g_h2h, b2, out);    // 7
}